// round 13
// baseline (speedup 1.0000x reference)
#include <cuda_runtime.h>
#include <cuda_fp16.h>
#include <math.h>
#include <stdint.h>

#define NB 512
#define NL 128
#define ND 512
#define NROWS ((size_t)NB * NL)   // 65536

// ---------------- scratch (static device globals) ----------------
// packed 2x fp16 per uint32; row = 256 uint32 = 512 cols = 1024 B
__device__ uint32_t g_A1h[NROWS * 256];   // gather(E,t1) fp16
__device__ uint32_t g_B2h[NROWS * 256];   // gather(E,t2) fp16
__device__ uint32_t g_Ch [NROWS * 256];   // C = A1 @ M, fp16
__device__ uint32_t g_Mth[ND * 256];      // Mt[n][k] fp16
__device__ float g_inv_na[NB], g_inv_nb[NB];
__device__ float g_rowm[NB * NL], g_colm[NB * NL];
__device__ float g_rows[NB * NL], g_cols[NB * NL];

// ---------------- helpers ----------------
__device__ __forceinline__ uint32_t smem_u32(const void* p) {
    uint32_t a;
    asm("{ .reg .u64 t; cvta.to.shared.u64 t, %1; cvt.u32.u64 %0, t; }" : "=r"(a) : "l"(p));
    return a;
}
__device__ __forceinline__ uint32_t swz(uint32_t o) { return o ^ ((o >> 3) & 0x70); }

#define CP16(dst, src) \
    asm volatile("cp.async.cg.shared.global [%0], [%1], 16;" :: "r"(dst), "l"(src))
#define CP_COMMIT() asm volatile("cp.async.commit_group;" ::: "memory")
#define CP_WAIT(n)  asm volatile("cp.async.wait_group %0;" :: "n"(n) : "memory")

__device__ __forceinline__ void ldm_x4(uint32_t* r, uint32_t addr) {
    asm volatile("ldmatrix.sync.aligned.m8n8.x4.shared.b16 {%0,%1,%2,%3}, [%4];"
        : "=r"(r[0]), "=r"(r[1]), "=r"(r[2]), "=r"(r[3]) : "r"(addr));
}
__device__ __forceinline__ void mma_f16(float* c, const uint32_t* a, const uint32_t* b) {
    asm volatile("mma.sync.aligned.m16n8k16.row.col.f32.f16.f16.f32 "
        "{%0,%1,%2,%3}, {%4,%5,%6,%7}, {%8,%9}, {%0,%1,%2,%3};"
        : "+f"(c[0]), "+f"(c[1]), "+f"(c[2]), "+f"(c[3])
        : "r"(a[0]), "r"(a[1]), "r"(a[2]), "r"(a[3]), "r"(b[0]), "r"(b[1]));
}
__device__ __forceinline__ uint32_t packh(float a, float b) {
    return ((uint32_t)__half_as_ushort(__float2half_rn(b)) << 16) |
           (uint32_t)__half_as_ushort(__float2half_rn(a));
}

// K=64 chunk, warp tile 32x64; A @ +0 (128 rows), B @ +16K
__device__ __forceinline__ void chunk_g1(uint32_t st, int lane, int m_base,
                                         int n_base, float acc[2][8][4]) {
    const int lrow = lane & 7, lmat = lane >> 3;
    const uint32_t a_row = (uint32_t)(m_base + (lmat & 1) * 8 + lrow) * 128;
    const uint32_t a_kb  = (uint32_t)((lmat >> 1) * 8) * 2;
    const uint32_t b_row = (uint32_t)(n_base + (lmat >> 1) * 8 + lrow) * 128;
    const uint32_t b_kb  = (uint32_t)((lmat & 1) * 8) * 2;
    #pragma unroll
    for (int ks = 0; ks < 4; ks++) {
        uint32_t Af[2][4];
        #pragma unroll
        for (int i = 0; i < 2; i++)
            ldm_x4(Af[i], st + swz(a_row + (uint32_t)i * 2048 + a_kb + ks * 32));
        #pragma unroll
        for (int j = 0; j < 4; j++) {
            uint32_t Bf[4];
            ldm_x4(Bf, st + 16384 + swz(b_row + (uint32_t)j * 2048 + b_kb + ks * 32));
            #pragma unroll
            for (int i = 0; i < 2; i++) {
                mma_f16(acc[i][2*j],   Af[i], &Bf[0]);
                mma_f16(acc[i][2*j+1], Af[i], &Bf[2]);
            }
        }
    }
}

// ---------------------------------------------------------------------------
// Kernel 0: transpose + fp16-pack att_mat -> g_Mth (Mt[n][k] = M[k][n])
// ---------------------------------------------------------------------------
__global__ __launch_bounds__(256) void prep_mt_kernel(const float* __restrict__ M) {
    __shared__ float t[32][33];
    const int n0 = blockIdx.x * 32, k0 = blockIdx.y * 32;
    const int tid = threadIdx.x;
    const int tx = tid & 31, ty = tid >> 5;
    #pragma unroll
    for (int j = 0; j < 32; j += 8)
        t[ty + j][tx] = M[(size_t)(k0 + ty + j) * ND + n0 + tx];
    __syncthreads();
    #pragma unroll
    for (int rep = 0; rep < 2; rep++) {
        int idx = rep * 256 + tid;
        int nl = idx >> 4, kp = idx & 15;
        g_Mth[(size_t)(n0 + nl) * 256 + (k0 >> 1) + kp] =
            packh(t[2 * kp][nl], t[2 * kp + 1][nl]);
    }
}

// ---------------------------------------------------------------------------
// Kernel 1: gather + fp16-pack + norms (fused), 512 threads / 2 rows per iter
// ---------------------------------------------------------------------------
__global__ __launch_bounds__(512) void prep_kernel(
    const int* __restrict__ t1c, const int* __restrict__ t2c,
    const float* __restrict__ E)
{
    const int b = blockIdx.x, tid = threadIdx.x;
    __shared__ int i1s[NL], i2s[NL];
    if (tid < NL) { i1s[tid] = t1c[b * NL + tid]; i2s[tid] = t2c[b * NL + tid]; }
    __syncthreads();
    const int col = tid & 255;
    const int hf  = tid >> 8;
    float s1 = 0.f, s2 = 0.f;
    #pragma unroll 4
    for (int l = hf; l < NL; l += 2) {
        float2 v1 = ((const float2*)(E + (size_t)i1s[l] * ND))[col];
        float2 v2 = ((const float2*)(E + (size_t)i2s[l] * ND))[col];
        s1 += v1.x * v1.x + v1.y * v1.y;
        s2 += v2.x * v2.x + v2.y * v2.y;
        size_t o = (size_t)(b * NL + l) * 256 + col;
        g_A1h[o] = packh(v1.x, v1.y);
        g_B2h[o] = packh(v2.x, v2.y);
    }
    __shared__ float sh1[16], sh2[16];
    #pragma unroll
    for (int o = 16; o; o >>= 1) {
        s1 += __shfl_xor_sync(0xffffffffu, s1, o);
        s2 += __shfl_xor_sync(0xffffffffu, s2, o);
    }
    if ((tid & 31) == 0) { sh1[tid >> 5] = s1; sh2[tid >> 5] = s2; }
    __syncthreads();
    if (tid < 16) {
        s1 = sh1[tid]; s2 = sh2[tid];
        #pragma unroll
        for (int o = 8; o; o >>= 1) {
            s1 += __shfl_xor_sync(0xffffu, s1, o);
            s2 += __shfl_xor_sync(0xffffu, s2, o);
        }
        if (tid == 0) { g_inv_na[b] = rsqrtf(s1); g_inv_nb[b] = rsqrtf(s2); }
    }
}

// ---------------------------------------------------------------------------
// Kernel 2: GEMM1 — C = A1 @ Mt^T (fp16), 128x256 tile, 512 thr (R11 exact)
// ---------------------------------------------------------------------------
#define G1_STAGE 49152
#define G1_SMEM  (2 * G1_STAGE + 1024)

__global__ __launch_bounds__(512, 1) void gemm1_kernel()
{
    extern __shared__ char smem_raw[];
    const uint32_t sb_raw = smem_u32(smem_raw);
    const uint32_t sb = (sb_raw + 1023) & ~1023u;
    const int tid = threadIdx.x;
    const int m0 = blockIdx.y * 128, n0 = blockIdx.x * 256;

    const char* srcA = (const char*)g_A1h + (size_t)m0 * 1024;
    const char* srcB = (const char*)g_Mth + (size_t)n0 * 1024;

    auto load_stage = [&](int c, int s) {
        const uint32_t stg = sb + s * G1_STAGE;
        #pragma unroll
        for (int q = 0; q < 2; q++) {     // A: 128 rows x 8 segs
            int sid = tid + q * 512;
            int r = sid >> 3, seg = sid & 7;
            uint32_t dst = stg + swz((uint32_t)(r * 128 + seg * 16));
            CP16(dst, srcA + (size_t)r * 1024 + c * 128 + seg * 16);
        }
        #pragma unroll
        for (int q = 0; q < 4; q++) {     // B: 256 rows x 8 segs
            int sid = tid + q * 512;
            int r = sid >> 3, seg = sid & 7;
            uint32_t dst = stg + 16384 + swz((uint32_t)(r * 128 + seg * 16));
            CP16(dst, srcB + (size_t)r * 1024 + c * 128 + seg * 16);
        }
    };

    float acc[2][8][4];
    #pragma unroll
    for (int i = 0; i < 2; i++)
        #pragma unroll
        for (int j = 0; j < 8; j++)
            #pragma unroll
            for (int q = 0; q < 4; q++) acc[i][j][q] = 0.f;

    load_stage(0, 0); CP_COMMIT();
    load_stage(1, 1); CP_COMMIT();
    CP_WAIT(1); __syncthreads();

    const int wid = tid >> 5, lane = tid & 31;
    const int m_base = (wid >> 2) * 32, n_base = (wid & 3) * 64;

    for (int c = 0; c < 8; c++) {
        chunk_g1(sb + (c & 1) * G1_STAGE, lane, m_base, n_base, acc);
        __syncthreads();
        if (c + 2 < 8) { load_stage(c + 2, c & 1); CP_COMMIT(); CP_WAIT(1); }
        else if (c == 6) { CP_WAIT(0); }
        __syncthreads();
    }

    // epilogue: fp16-pack acc -> g_Ch
    #pragma unroll
    for (int i = 0; i < 2; i++) {
        int gr = m0 + m_base + i * 16 + (lane >> 2);
        #pragma unroll
        for (int j8 = 0; j8 < 8; j8++) {
            int gc = n0 + n_base + j8 * 8 + (lane & 3) * 2;
            g_Ch[(size_t)gr * 256 + (gc >> 1)]       = packh(acc[i][j8][0], acc[i][j8][1]);
            g_Ch[(size_t)(gr + 8) * 256 + (gc >> 1)] = packh(acc[i][j8][2], acc[i][j8][3]);
        }
    }
}

// ---------------------------------------------------------------------------
// Kernel 3: GEMM2 — S[b] = tanh(scale * C[b] @ B2[b]^T), fused means
//   k-split: warps 0-7 do k=0..255, warps 8-15 do k=256..511, 32x64 tiles.
//   Pair-stage: [Clo 16K | Blo 16K | Chi 16K | Bhi 16K] = 64KB, 2 stages.
// ---------------------------------------------------------------------------
#define G2_STAGE 65536
#define G2_SMEM  (2 * G2_STAGE + 1024)

__global__ __launch_bounds__(512, 1) void gemm2_kernel(float* __restrict__ outS)
{
    extern __shared__ char smem_raw[];
    const uint32_t sb_raw = smem_u32(smem_raw);
    const uint32_t sb = (sb_raw + 1023) & ~1023u;
    char* smem = smem_raw + (sb - sb_raw);
    const int tid = threadIdx.x;
    const int b = blockIdx.x;

    const char* srcC = (const char*)g_Ch  + (size_t)b * NL * 1024;
    const char* srcB = (const char*)g_B2h + (size_t)b * NL * 1024;

    // load chunk pair (p, p+4): lo half -> +0/+16K, hi half -> +32K/+48K
    auto load_pair = [&](int p, int s) {
        const uint32_t stg = sb + s * G2_STAGE;
        #pragma unroll
        for (int q = 0; q < 2; q++) {
            int sid = tid + q * 512;
            int r = sid >> 3, seg = sid & 7;
            uint32_t off = swz((uint32_t)(r * 128 + seg * 16));
            size_t lo = (size_t)r * 1024 + p * 128 + seg * 16;
            size_t hi = (size_t)r * 1024 + (p + 4) * 128 + seg * 16;
            CP16(stg + off,         srcC + lo);
            CP16(stg + 16384 + off, srcB + lo);
            CP16(stg + 32768 + off, srcC + hi);
            CP16(stg + 49152 + off, srcB + hi);
        }
    };

    float acc[2][8][4];
    #pragma unroll
    for (int i = 0; i < 2; i++)
        #pragma unroll
        for (int j = 0; j < 8; j++)
            #pragma unroll
            for (int q = 0; q < 4; q++) acc[i][j][q] = 0.f;

    load_pair(0, 0); CP_COMMIT();
    load_pair(1, 1); CP_COMMIT();
    CP_WAIT(1); __syncthreads();

    const int wid = tid >> 5, lane = tid & 31;
    const int half = wid >> 3;            // 0 = k-lo, 1 = k-hi
    const int w8 = wid & 7;
    const int m_base = (w8 >> 1) * 32, n_base = (w8 & 1) * 64;
    const uint32_t hoff = (uint32_t)half * 32768;

    for (int ci = 0; ci < 4; ci++) {
        chunk_g1(sb + (ci & 1) * G2_STAGE + hoff, lane, m_base, n_base, acc);
        __syncthreads();
        if (ci + 2 < 4) { load_pair(ci + 2, ci & 1); CP_COMMIT(); CP_WAIT(1); }
        else if (ci == 2) { CP_WAIT(0); }
        __syncthreads();
    }

    // ---- epilogue: combine halves + tanh + S store + fused means ----
    float* Sbuf = (float*)smem;              // 128 x 132 pitch f32 (67.6KB)
    float* rs   = Sbuf + 128 * 132;
    float* cs   = rs + 128;

    if (half == 1) {
        #pragma unroll
        for (int i = 0; i < 2; i++) {
            int r0 = m_base + i * 16 + (lane >> 2);
            #pragma unroll
            for (int j8 = 0; j8 < 8; j8++) {
                int col = n_base + j8 * 8 + (lane & 3) * 2;
                Sbuf[r0 * 132 + col]           = acc[i][j8][0];
                Sbuf[r0 * 132 + col + 1]       = acc[i][j8][1];
                Sbuf[(r0 + 8) * 132 + col]     = acc[i][j8][2];
                Sbuf[(r0 + 8) * 132 + col + 1] = acc[i][j8][3];
            }
        }
    }
    if (tid < 128) { rs[tid] = 0.f; cs[tid] = 0.f; }
    __syncthreads();

    if (half == 0) {
        const float scale = g_inv_na[b] * g_inv_nb[b];
        float* Sb = outS + (size_t)b * NL * NL;
        float cpart0[8], cpart1[8];
        #pragma unroll
        for (int j8 = 0; j8 < 8; j8++) { cpart0[j8] = 0.f; cpart1[j8] = 0.f; }
        float rpart[2][2] = {{0.f, 0.f}, {0.f, 0.f}};

        #pragma unroll
        for (int i = 0; i < 2; i++) {
            int r0 = m_base + i * 16 + (lane >> 2);
            #pragma unroll
            for (int j8 = 0; j8 < 8; j8++) {
                int col = n_base + j8 * 8 + (lane & 3) * 2;
                float v0 = tanhf((acc[i][j8][0] + Sbuf[r0 * 132 + col]) * scale);
                float v1 = tanhf((acc[i][j8][1] + Sbuf[r0 * 132 + col + 1]) * scale);
                float v2 = tanhf((acc[i][j8][2] + Sbuf[(r0 + 8) * 132 + col]) * scale);
                float v3 = tanhf((acc[i][j8][3] + Sbuf[(r0 + 8) * 132 + col + 1]) * scale);
                float* p = Sb + (size_t)r0 * NL + col;
                *(float2*)p = make_float2(v0, v1);
                *(float2*)(p + 8 * NL) = make_float2(v2, v3);
                rpart[0][i] += v0 + v1;
                rpart[1][i] += v2 + v3;
                cpart0[j8] += v0 + v2;
                cpart1[j8] += v1 + v3;
            }
        }
        #pragma unroll
        for (int i = 0; i < 2; i++) {
            atomicAdd(&rs[m_base + i * 16 + (lane >> 2)], rpart[0][i]);
            atomicAdd(&rs[m_base + i * 16 + (lane >> 2) + 8], rpart[1][i]);
        }
        #pragma unroll
        for (int j8 = 0; j8 < 8; j8++) {
            atomicAdd(&cs[n_base + j8 * 8 + (lane & 3) * 2], cpart0[j8]);
            atomicAdd(&cs[n_base + j8 * 8 + (lane & 3) * 2 + 1], cpart1[j8]);
        }
    }
    __syncthreads();
    if (tid < 128) {
        g_rowm[b * NL + tid] = rs[tid] * (1.0f / NL);
        g_colm[b * NL + tid] = cs[tid] * (1.0f / NL);
    }
}

// ---------------------------------------------------------------------------
// Kernel 4: softmax over precomputed means (tiny)
// ---------------------------------------------------------------------------
__global__ __launch_bounds__(128) void softmax_kernel()
{
    const int b = blockIdx.x, t = threadIdx.x;
    __shared__ float buf[128];
    float v = g_rowm[b * NL + t];
    buf[t] = v; __syncthreads();
    for (int s = 64; s; s >>= 1) { if (t < s) buf[t] = fmaxf(buf[t], buf[t + s]); __syncthreads(); }
    float mx = buf[0]; __syncthreads();
    float e = expf(v - mx);
    buf[t] = e; __syncthreads();
    for (int s = 64; s; s >>= 1) { if (t < s) buf[t] += buf[t + s]; __syncthreads(); }
    g_rows[b * NL + t] = e / buf[0];
    __syncthreads();
    v = g_colm[b * NL + t];
    buf[t] = v; __syncthreads();
    for (int s = 64; s; s >>= 1) { if (t < s) buf[t] = fmaxf(buf[t], buf[t + s]); __syncthreads(); }
    mx = buf[0]; __syncthreads();
    e = expf(v - mx);
    buf[t] = e; __syncthreads();
    for (int s = 64; s; s >>= 1) { if (t < s) buf[t] += buf[t + s]; __syncthreads(); }
    g_cols[b * NL + t] = e / buf[0];
}

// ---------------------------------------------------------------------------
// Kernel 5: weighted reduce from fp16 arrays (sequential reads)
// ---------------------------------------------------------------------------
__global__ __launch_bounds__(256) void final_kernel(
    const float* __restrict__ w, const float* __restrict__ bp,
    float* __restrict__ out)
{
    const int b = blockIdx.x, tid = threadIdx.x;
    __shared__ float rw[NL], cw[NL];
    if (tid < NL) { rw[tid] = g_rows[b * NL + tid]; cw[tid] = g_cols[b * NL + tid]; }
    __syncthreads();
    float ax = 0.f, ay = 0.f, bx = 0.f, by = 0.f;
    #pragma unroll 4
    for (int l = 0; l < NL; l++) {
        size_t o = (size_t)(b * NL + l) * 256 + tid;
        uint32_t av = g_A1h[o], bv = g_B2h[o];
        __half2 ah = *reinterpret_cast<__half2*>(&av);
        __half2 bh = *reinterpret_cast<__half2*>(&bv);
        float wr = rw[l], wc = cw[l];
        ax += wr * __half2float(ah.x);  ay += wr * __half2float(ah.y);
        bx += wc * __half2float(bh.x);  by += wc * __half2float(bh.y);
    }
    float2 wv = ((const float2*)w)[tid];
    float part = (ax * bx * wv.x + ay * by * wv.y) * (g_inv_na[b] * g_inv_nb[b]);
    __shared__ float sh[8];
    #pragma unroll
    for (int o = 16; o; o >>= 1) part += __shfl_xor_sync(0xffffffffu, part, o);
    if ((tid & 31) == 0) sh[tid >> 5] = part;
    __syncthreads();
    if (tid < 8) {
        part = sh[tid];
        #pragma unroll
        for (int o = 4; o; o >>= 1) part += __shfl_xor_sync(0xffu, part, o);
        if (tid == 0) out[b] = part + bp[0];
    }
}

// ---------------------------------------------------------------------------
extern "C" void kernel_launch(void* const* d_in, const int* in_sizes, int n_in,
                              void* d_out, int out_size)
{
    (void)in_sizes; (void)n_in; (void)out_size;
    const int*   t1c = (const int*)d_in[2];
    const int*   t2c = (const int*)d_in[3];
    const float* E   = (const float*)d_in[4];
    const float* M   = (const float*)d_in[5];
    const float* w   = (const float*)d_in[6];
    const float* bp  = (const float*)d_in[7];
    float* out  = (float*)d_out;
    float* outS = out + NB;   // output = concat(logits[512], S[512*128*128])

    cudaFuncSetAttribute(gemm1_kernel, cudaFuncAttributeMaxDynamicSharedMemorySize, G1_SMEM);
    cudaFuncSetAttribute(gemm2_kernel, cudaFuncAttributeMaxDynamicSharedMemorySize, G2_SMEM);

    prep_mt_kernel<<<dim3(16, 16), 256>>>(M);
    prep_kernel<<<NB, 512>>>(t1c, t2c, E);
    gemm1_kernel<<<dim3(2, 512), 512, G1_SMEM>>>();
    gemm2_kernel<<<NB, 512, G2_SMEM>>>(outS);
    softmax_kernel<<<NB, 128>>>();
    final_kernel<<<NB, 256>>>(w, bp, out);
}

// round 14
// speedup vs baseline: 1.1541x; 1.1541x over previous
#include <cuda_runtime.h>
#include <cuda_fp16.h>
#include <math.h>
#include <stdint.h>

#define NB 512
#define NL 128
#define ND 512
#define NROWS ((size_t)NB * NL)   // 65536

// ---------------- scratch (static device globals) ----------------
// packed 2x fp16 per uint32; row = 256 uint32 = 512 cols = 1024 B
__device__ uint32_t g_A1h[NROWS * 256];   // gather(E,t1) fp16
__device__ uint32_t g_B2h[NROWS * 256];   // gather(E,t2) fp16
__device__ uint32_t g_Ch [NROWS * 256];   // C = A1 @ M, fp16
__device__ uint32_t g_Mth[ND * 256];      // Mt[n][k] fp16
__device__ float g_inv_na[NB], g_inv_nb[NB];
__device__ float g_rowm[NB * NL], g_colm[NB * NL];

// ---------------- helpers ----------------
__device__ __forceinline__ uint32_t smem_u32(const void* p) {
    uint32_t a;
    asm("{ .reg .u64 t; cvta.to.shared.u64 t, %1; cvt.u32.u64 %0, t; }" : "=r"(a) : "l"(p));
    return a;
}
__device__ __forceinline__ uint32_t swz(uint32_t o) { return o ^ ((o >> 3) & 0x70); }

#define CP16(dst, src) \
    asm volatile("cp.async.cg.shared.global [%0], [%1], 16;" :: "r"(dst), "l"(src))
#define CP_COMMIT() asm volatile("cp.async.commit_group;" ::: "memory")
#define CP_WAIT(n)  asm volatile("cp.async.wait_group %0;" :: "n"(n) : "memory")

__device__ __forceinline__ void ldm_x4(uint32_t* r, uint32_t addr) {
    asm volatile("ldmatrix.sync.aligned.m8n8.x4.shared.b16 {%0,%1,%2,%3}, [%4];"
        : "=r"(r[0]), "=r"(r[1]), "=r"(r[2]), "=r"(r[3]) : "r"(addr));
}
__device__ __forceinline__ void mma_f16(float* c, const uint32_t* a, const uint32_t* b) {
    asm volatile("mma.sync.aligned.m16n8k16.row.col.f32.f16.f16.f32 "
        "{%0,%1,%2,%3}, {%4,%5,%6,%7}, {%8,%9}, {%0,%1,%2,%3};"
        : "+f"(c[0]), "+f"(c[1]), "+f"(c[2]), "+f"(c[3])
        : "r"(a[0]), "r"(a[1]), "r"(a[2]), "r"(a[3]), "r"(b[0]), "r"(b[1]));
}
__device__ __forceinline__ uint32_t packh(float a, float b) {
    return ((uint32_t)__half_as_ushort(__float2half_rn(b)) << 16) |
           (uint32_t)__half_as_ushort(__float2half_rn(a));
}

// GEMM1 chunk: warp tile 32x64; A @ 0, B @ +16K (single fp16 product)
__device__ __forceinline__ void chunk_g1(uint32_t st, int lane, int m_base,
                                         int n_base, float acc[2][8][4]) {
    const int lrow = lane & 7, lmat = lane >> 3;
    const uint32_t a_row = (uint32_t)(m_base + (lmat & 1) * 8 + lrow) * 128;
    const uint32_t a_kb  = (uint32_t)((lmat >> 1) * 8) * 2;
    const uint32_t b_row = (uint32_t)(n_base + (lmat >> 1) * 8 + lrow) * 128;
    const uint32_t b_kb  = (uint32_t)((lmat & 1) * 8) * 2;
    #pragma unroll
    for (int ks = 0; ks < 4; ks++) {
        uint32_t Af[2][4];
        #pragma unroll
        for (int i = 0; i < 2; i++)
            ldm_x4(Af[i], st + swz(a_row + (uint32_t)i * 2048 + a_kb + ks * 32));
        #pragma unroll
        for (int j = 0; j < 4; j++) {
            uint32_t Bf[4];
            ldm_x4(Bf, st + 16384 + swz(b_row + (uint32_t)j * 2048 + b_kb + ks * 32));
            #pragma unroll
            for (int i = 0; i < 2; i++) {
                mma_f16(acc[i][2*j],   Af[i], &Bf[0]);
                mma_f16(acc[i][2*j+1], Af[i], &Bf[2]);
            }
        }
    }
}

// GEMM2 chunk: warp tile 32x32; C @ 0, B @ +16K (single fp16 product)
__device__ __forceinline__ void chunk_g2(uint32_t st, int lane, int m_base,
                                         int n_base, float acc[2][4][4]) {
    const int lrow = lane & 7, lmat = lane >> 3;
    const uint32_t a_row = (uint32_t)(m_base + (lmat & 1) * 8 + lrow) * 128;
    const uint32_t a_kb  = (uint32_t)((lmat >> 1) * 8) * 2;
    const uint32_t b_row = (uint32_t)(n_base + (lmat >> 1) * 8 + lrow) * 128;
    const uint32_t b_kb  = (uint32_t)((lmat & 1) * 8) * 2;
    #pragma unroll
    for (int ks = 0; ks < 4; ks++) {
        uint32_t Af[2][4];
        #pragma unroll
        for (int i = 0; i < 2; i++)
            ldm_x4(Af[i], st + swz(a_row + (uint32_t)i * 2048 + a_kb + ks * 32));
        #pragma unroll
        for (int j = 0; j < 2; j++) {
            uint32_t Bf[4];
            ldm_x4(Bf, st + 16384 + swz(b_row + (uint32_t)j * 2048 + b_kb + ks * 32));
            #pragma unroll
            for (int i = 0; i < 2; i++) {
                mma_f16(acc[i][2*j],   Af[i], &Bf[0]);
                mma_f16(acc[i][2*j+1], Af[i], &Bf[2]);
            }
        }
    }
}

// ---------------------------------------------------------------------------
// Kernel 0: transpose + fp16-pack att_mat -> g_Mth (Mt[n][k] = M[k][n])
// ---------------------------------------------------------------------------
__global__ __launch_bounds__(256) void prep_mt_kernel(const float* __restrict__ M) {
    __shared__ float t[32][33];
    const int n0 = blockIdx.x * 32, k0 = blockIdx.y * 32;
    const int tid = threadIdx.x;
    const int tx = tid & 31, ty = tid >> 5;
    #pragma unroll
    for (int j = 0; j < 32; j += 8)
        t[ty + j][tx] = M[(size_t)(k0 + ty + j) * ND + n0 + tx];
    __syncthreads();
    #pragma unroll
    for (int rep = 0; rep < 2; rep++) {
        int idx = rep * 256 + tid;
        int nl = idx >> 4, kp = idx & 15;
        g_Mth[(size_t)(n0 + nl) * 256 + (k0 >> 1) + kp] =
            packh(t[2 * kp][nl], t[2 * kp + 1][nl]);
    }
}

// ---------------------------------------------------------------------------
// Kernel 1: gather + fp16-pack + norms (fused)  [R11 exact]
// ---------------------------------------------------------------------------
__global__ __launch_bounds__(256) void prep_kernel(
    const int* __restrict__ t1c, const int* __restrict__ t2c,
    const float* __restrict__ E)
{
    const int b = blockIdx.x, tid = threadIdx.x;
    __shared__ int i1s[NL], i2s[NL];
    if (tid < NL) { i1s[tid] = t1c[b * NL + tid]; i2s[tid] = t2c[b * NL + tid]; }
    __syncthreads();
    float s1 = 0.f, s2 = 0.f;
    #pragma unroll 2
    for (int l = 0; l < NL; l++) {
        float2 v1 = ((const float2*)(E + (size_t)i1s[l] * ND))[tid];
        float2 v2 = ((const float2*)(E + (size_t)i2s[l] * ND))[tid];
        s1 += v1.x * v1.x + v1.y * v1.y;
        s2 += v2.x * v2.x + v2.y * v2.y;
        size_t o = (size_t)(b * NL + l) * 256 + tid;
        g_A1h[o] = packh(v1.x, v1.y);
        g_B2h[o] = packh(v2.x, v2.y);
    }
    __shared__ float sh1[8], sh2[8];
    #pragma unroll
    for (int o = 16; o; o >>= 1) {
        s1 += __shfl_xor_sync(0xffffffffu, s1, o);
        s2 += __shfl_xor_sync(0xffffffffu, s2, o);
    }
    if ((tid & 31) == 0) { sh1[tid >> 5] = s1; sh2[tid >> 5] = s2; }
    __syncthreads();
    if (tid < 8) {
        s1 = sh1[tid]; s2 = sh2[tid];
        #pragma unroll
        for (int o = 4; o; o >>= 1) {
            s1 += __shfl_xor_sync(0xffu, s1, o);
            s2 += __shfl_xor_sync(0xffu, s2, o);
        }
        if (tid == 0) { g_inv_na[b] = rsqrtf(s1); g_inv_nb[b] = rsqrtf(s2); }
    }
}

// ---------------------------------------------------------------------------
// Kernel 2: GEMM1 — C = A1 @ Mt^T (both fp16), 128x256 tile, 512 thr [R11 exact]
// ---------------------------------------------------------------------------
#define G1_STAGE 49152
#define G1_SMEM  (2 * G1_STAGE + 1024)

__global__ __launch_bounds__(512, 1) void gemm1_kernel()
{
    extern __shared__ char smem_raw[];
    const uint32_t sb_raw = smem_u32(smem_raw);
    const uint32_t sb = (sb_raw + 1023) & ~1023u;
    const int tid = threadIdx.x;
    const int m0 = blockIdx.y * 128, n0 = blockIdx.x * 256;

    const char* srcA = (const char*)g_A1h + (size_t)m0 * 1024;
    const char* srcB = (const char*)g_Mth + (size_t)n0 * 1024;

    auto load_stage = [&](int c, int s) {
        const uint32_t stg = sb + s * G1_STAGE;
        #pragma unroll
        for (int q = 0; q < 2; q++) {     // A: 128 rows x 8 segs
            int sid = tid + q * 512;
            int r = sid >> 3, seg = sid & 7;
            uint32_t dst = stg + swz((uint32_t)(r * 128 + seg * 16));
            CP16(dst, srcA + (size_t)r * 1024 + c * 128 + seg * 16);
        }
        #pragma unroll
        for (int q = 0; q < 4; q++) {     // B: 256 rows x 8 segs
            int sid = tid + q * 512;
            int r = sid >> 3, seg = sid & 7;
            uint32_t dst = stg + 16384 + swz((uint32_t)(r * 128 + seg * 16));
            CP16(dst, srcB + (size_t)r * 1024 + c * 128 + seg * 16);
        }
    };

    float acc[2][8][4];
    #pragma unroll
    for (int i = 0; i < 2; i++)
        #pragma unroll
        for (int j = 0; j < 8; j++)
            #pragma unroll
            for (int q = 0; q < 4; q++) acc[i][j][q] = 0.f;

    load_stage(0, 0); CP_COMMIT();
    load_stage(1, 1); CP_COMMIT();
    CP_WAIT(1); __syncthreads();

    const int wid = tid >> 5, lane = tid & 31;
    const int m_base = (wid >> 2) * 32, n_base = (wid & 3) * 64;

    for (int c = 0; c < 8; c++) {
        chunk_g1(sb + (c & 1) * G1_STAGE, lane, m_base, n_base, acc);
        __syncthreads();
        if (c + 2 < 8) { load_stage(c + 2, c & 1); CP_COMMIT(); CP_WAIT(1); }
        else if (c == 6) { CP_WAIT(0); }
        __syncthreads();
    }

    // epilogue: fp16-pack acc -> g_Ch
    #pragma unroll
    for (int i = 0; i < 2; i++) {
        int gr = m0 + m_base + i * 16 + (lane >> 2);
        #pragma unroll
        for (int j8 = 0; j8 < 8; j8++) {
            int gc = n0 + n_base + j8 * 8 + (lane & 3) * 2;
            g_Ch[(size_t)gr * 256 + (gc >> 1)]       = packh(acc[i][j8][0], acc[i][j8][1]);
            g_Ch[(size_t)(gr + 8) * 256 + (gc >> 1)] = packh(acc[i][j8][2], acc[i][j8][3]);
        }
    }
}

// ---------------------------------------------------------------------------
// Kernel 3: GEMM2 — S[b] = tanh(scale * C[b] @ B2[b]^T), fused means [R11 exact]
//   512 thr, 16 warps (4x4), warp tile 32x32; stage C 16K | B 16K = 32KB x 3
// ---------------------------------------------------------------------------
#define G2_STAGE 32768
#define G2_SMEM  (3 * G2_STAGE + 1024)

__global__ __launch_bounds__(512, 1) void gemm2_kernel(float* __restrict__ outS)
{
    extern __shared__ char smem_raw[];
    const uint32_t sb_raw = smem_u32(smem_raw);
    const uint32_t sb = (sb_raw + 1023) & ~1023u;
    char* smem = smem_raw + (sb - sb_raw);
    const int tid = threadIdx.x;
    const int b = blockIdx.x;

    const char* srcC = (const char*)g_Ch  + (size_t)b * NL * 1024;
    const char* srcB = (const char*)g_B2h + (size_t)b * NL * 1024;

    auto load_stage = [&](int c, int s) {
        const uint32_t stg = sb + s * G2_STAGE;
        #pragma unroll
        for (int q = 0; q < 2; q++) {
            int sid = tid + q * 512;
            int r = sid >> 3, seg = sid & 7;
            uint32_t dst = stg + swz((uint32_t)(r * 128 + seg * 16));
            size_t so = (size_t)r * 1024 + c * 128 + seg * 16;
            CP16(dst, srcC + so);
            CP16(dst + 16384, srcB + so);
        }
    };

    float acc[2][4][4];
    #pragma unroll
    for (int i = 0; i < 2; i++)
        #pragma unroll
        for (int j = 0; j < 4; j++)
            #pragma unroll
            for (int q = 0; q < 4; q++) acc[i][j][q] = 0.f;

    load_stage(0, 0); CP_COMMIT();
    load_stage(1, 1); CP_COMMIT();
    load_stage(2, 2); CP_COMMIT();
    CP_WAIT(2); __syncthreads();

    const int wid = tid >> 5, lane = tid & 31;
    const int m_base = (wid >> 2) * 32, n_base = (wid & 3) * 32;

    for (int c = 0; c < 8; c++) {
        chunk_g2(sb + (c % 3) * G2_STAGE, lane, m_base, n_base, acc);
        __syncthreads();
        if (c + 3 < 8)      { load_stage(c + 3, c % 3); CP_COMMIT(); CP_WAIT(2); }
        else if (c == 5)    { CP_WAIT(1); }
        else if (c == 6)    { CP_WAIT(0); }
        __syncthreads();
    }

    // epilogue: tanh + S store + fused row/col means
    float* rs = (float*)smem;
    float* cs = rs + 128;
    if (tid < 128) { rs[tid] = 0.f; cs[tid] = 0.f; }
    __syncthreads();

    const float scale = g_inv_na[b] * g_inv_nb[b];
    float* Sb = outS + (size_t)b * NL * NL;
    float cpart0[4], cpart1[4];
    #pragma unroll
    for (int j8 = 0; j8 < 4; j8++) { cpart0[j8] = 0.f; cpart1[j8] = 0.f; }
    float rpart[2][2] = {{0.f, 0.f}, {0.f, 0.f}};

    #pragma unroll
    for (int i = 0; i < 2; i++) {
        int r0 = m_base + i * 16 + (lane >> 2);
        #pragma unroll
        for (int j8 = 0; j8 < 4; j8++) {
            int col = n_base + j8 * 8 + (lane & 3) * 2;
            float v0 = tanhf(acc[i][j8][0] * scale);
            float v1 = tanhf(acc[i][j8][1] * scale);
            float v2 = tanhf(acc[i][j8][2] * scale);
            float v3 = tanhf(acc[i][j8][3] * scale);
            float* p = Sb + (size_t)r0 * NL + col;
            *(float2*)p = make_float2(v0, v1);
            *(float2*)(p + 8 * NL) = make_float2(v2, v3);
            rpart[i][0] += v0 + v1;
            rpart[i][1] += v2 + v3;
            cpart0[j8] += v0 + v2;
            cpart1[j8] += v1 + v3;
        }
    }
    #pragma unroll
    for (int i = 0; i < 2; i++) {
        atomicAdd(&rs[m_base + i * 16 + (lane >> 2)], rpart[i][0]);
        atomicAdd(&rs[m_base + i * 16 + (lane >> 2) + 8], rpart[i][1]);
    }
    #pragma unroll
    for (int j8 = 0; j8 < 4; j8++) {
        atomicAdd(&cs[n_base + j8 * 8 + (lane & 3) * 2], cpart0[j8]);
        atomicAdd(&cs[n_base + j8 * 8 + (lane & 3) * 2 + 1], cpart1[j8]);
    }
    __syncthreads();
    if (tid < 128) {
        g_rowm[b * NL + tid] = rs[tid] * (1.0f / NL);
        g_colm[b * NL + tid] = cs[tid] * (1.0f / NL);
    }
}

// ---------------------------------------------------------------------------
// Kernel 4: fused softmax (rows & cols concurrently) + weighted reduce + logits
// ---------------------------------------------------------------------------
__global__ __launch_bounds__(256) void final_kernel(
    const float* __restrict__ w, const float* __restrict__ bp,
    float* __restrict__ out)
{
    const int b = blockIdx.x, tid = threadIdx.x;
    __shared__ float rw[NL], cw[NL], red[256];
    // --- dual softmax: threads 0-127 -> rows, 128-255 -> cols ---
    const int h = tid >> 7, t = tid & 127;
    float v = h ? g_colm[b * NL + t] : g_rowm[b * NL + t];
    red[tid] = v;
    __syncthreads();
    #pragma unroll
    for (int s = 64; s; s >>= 1) {
        if (t < s) red[h * 128 + t] = fmaxf(red[h * 128 + t], red[h * 128 + t + s]);
        __syncthreads();
    }
    float mx = red[h * 128];
    __syncthreads();
    float e = expf(v - mx);
    red[tid] = e;
    __syncthreads();
    #pragma unroll
    for (int s = 64; s; s >>= 1) {
        if (t < s) red[h * 128 + t] += red[h * 128 + t + s];
        __syncthreads();
    }
    float sm = e / red[h * 128];
    if (h == 0) rw[t] = sm; else cw[t] = sm;
    __syncthreads();

    // --- weighted reduce from fp16 arrays (sequential reads) ---
    float ax = 0.f, ay = 0.f, bx = 0.f, by = 0.f;
    #pragma unroll 4
    for (int l = 0; l < NL; l++) {
        size_t o = (size_t)(b * NL + l) * 256 + tid;
        uint32_t av = g_A1h[o], bv = g_B2h[o];
        __half2 ah = *reinterpret_cast<__half2*>(&av);
        __half2 bh = *reinterpret_cast<__half2*>(&bv);
        float wr = rw[l], wc = cw[l];
        ax += wr * __half2float(ah.x);  ay += wr * __half2float(ah.y);
        bx += wc * __half2float(bh.x);  by += wc * __half2float(bh.y);
    }
    float2 wv = ((const float2*)w)[tid];
    float part = (ax * bx * wv.x + ay * by * wv.y) * (g_inv_na[b] * g_inv_nb[b]);
    __shared__ float sh[8];
    #pragma unroll
    for (int o = 16; o; o >>= 1) part += __shfl_xor_sync(0xffffffffu, part, o);
    if ((tid & 31) == 0) sh[tid >> 5] = part;
    __syncthreads();
    if (tid < 8) {
        part = sh[tid];
        #pragma unroll
        for (int o = 4; o; o >>= 1) part += __shfl_xor_sync(0xffu, part, o);
        if (tid == 0) out[b] = part + bp[0];
    }
}

// ---------------------------------------------------------------------------
extern "C" void kernel_launch(void* const* d_in, const int* in_sizes, int n_in,
                              void* d_out, int out_size)
{
    (void)in_sizes; (void)n_in; (void)out_size;
    const int*   t1c = (const int*)d_in[2];
    const int*   t2c = (const int*)d_in[3];
    const float* E   = (const float*)d_in[4];
    const float* M   = (const float*)d_in[5];
    const float* w   = (const float*)d_in[6];
    const float* bp  = (const float*)d_in[7];
    float* out  = (float*)d_out;
    float* outS = out + NB;   // output = concat(logits[512], S[512*128*128])

    cudaFuncSetAttribute(gemm1_kernel, cudaFuncAttributeMaxDynamicSharedMemorySize, G1_SMEM);
    cudaFuncSetAttribute(gemm2_kernel, cudaFuncAttributeMaxDynamicSharedMemorySize, G2_SMEM);

    prep_mt_kernel<<<dim3(16, 16), 256>>>(M);
    prep_kernel<<<NB, 256>>>(t1c, t2c, E);
    gemm1_kernel<<<dim3(2, 512), 512, G1_SMEM>>>();
    gemm2_kernel<<<NB, 512, G2_SMEM>>>(outS);
    final_kernel<<<NB, 256>>>(w, bp, out);
}

// round 15
// speedup vs baseline: 1.1890x; 1.0302x over previous
#include <cuda_runtime.h>
#include <cuda_fp16.h>
#include <math.h>
#include <stdint.h>

#define NB 512
#define NL 128
#define ND 512
#define NROWS ((size_t)NB * NL)   // 65536

// ---------------- scratch (static device globals) ----------------
// packed 2x fp16 per uint32; row = 256 uint32 = 512 cols = 1024 B
__device__ uint32_t g_A1h[NROWS * 256];   // gather(E,t1) fp16
__device__ uint32_t g_B2h[NROWS * 256];   // gather(E,t2) fp16
__device__ uint32_t g_Ch [NROWS * 256];   // C = A1 @ M, fp16
__device__ uint32_t g_Mth[ND * 256];      // Mt[n][k] fp16
__device__ float g_inv_na[NB], g_inv_nb[NB];
__device__ float g_rowm[NB * NL], g_colm[NB * NL];

// ---------------- helpers ----------------
__device__ __forceinline__ uint32_t smem_u32(const void* p) {
    uint32_t a;
    asm("{ .reg .u64 t; cvta.to.shared.u64 t, %1; cvt.u32.u64 %0, t; }" : "=r"(a) : "l"(p));
    return a;
}
__device__ __forceinline__ uint32_t swz(uint32_t o) { return o ^ ((o >> 3) & 0x70); }

#define CP16(dst, src) \
    asm volatile("cp.async.cg.shared.global [%0], [%1], 16;" :: "r"(dst), "l"(src))
#define CP_COMMIT() asm volatile("cp.async.commit_group;" ::: "memory")
#define CP_WAIT(n)  asm volatile("cp.async.wait_group %0;" :: "n"(n) : "memory")

__device__ __forceinline__ void ldm_x4(uint32_t* r, uint32_t addr) {
    asm volatile("ldmatrix.sync.aligned.m8n8.x4.shared.b16 {%0,%1,%2,%3}, [%4];"
        : "=r"(r[0]), "=r"(r[1]), "=r"(r[2]), "=r"(r[3]) : "r"(addr));
}
__device__ __forceinline__ void mma_f16(float* c, const uint32_t* a, const uint32_t* b) {
    asm volatile("mma.sync.aligned.m16n8k16.row.col.f32.f16.f16.f32 "
        "{%0,%1,%2,%3}, {%4,%5,%6,%7}, {%8,%9}, {%0,%1,%2,%3};"
        : "+f"(c[0]), "+f"(c[1]), "+f"(c[2]), "+f"(c[3])
        : "r"(a[0]), "r"(a[1]), "r"(a[2]), "r"(a[3]), "r"(b[0]), "r"(b[1]));
}
__device__ __forceinline__ uint32_t packh(float a, float b) {
    return ((uint32_t)__half_as_ushort(__float2half_rn(b)) << 16) |
           (uint32_t)__half_as_ushort(__float2half_rn(a));
}

// K=64 chunk, warp tile 32x64; A @ 0 (128 rows), B @ +16K
__device__ __forceinline__ void chunk_g1(uint32_t st, int lane, int m_base,
                                         int n_base, float acc[2][8][4]) {
    const int lrow = lane & 7, lmat = lane >> 3;
    const uint32_t a_row = (uint32_t)(m_base + (lmat & 1) * 8 + lrow) * 128;
    const uint32_t a_kb  = (uint32_t)((lmat >> 1) * 8) * 2;
    const uint32_t b_row = (uint32_t)(n_base + (lmat >> 1) * 8 + lrow) * 128;
    const uint32_t b_kb  = (uint32_t)((lmat & 1) * 8) * 2;
    #pragma unroll
    for (int ks = 0; ks < 4; ks++) {
        uint32_t Af[2][4];
        #pragma unroll
        for (int i = 0; i < 2; i++)
            ldm_x4(Af[i], st + swz(a_row + (uint32_t)i * 2048 + a_kb + ks * 32));
        #pragma unroll
        for (int j = 0; j < 4; j++) {
            uint32_t Bf[4];
            ldm_x4(Bf, st + 16384 + swz(b_row + (uint32_t)j * 2048 + b_kb + ks * 32));
            #pragma unroll
            for (int i = 0; i < 2; i++) {
                mma_f16(acc[i][2*j],   Af[i], &Bf[0]);
                mma_f16(acc[i][2*j+1], Af[i], &Bf[2]);
            }
        }
    }
}

// ---------------------------------------------------------------------------
// Kernel 0: transpose + fp16-pack att_mat -> g_Mth (Mt[n][k] = M[k][n])
// ---------------------------------------------------------------------------
__global__ __launch_bounds__(256) void prep_mt_kernel(const float* __restrict__ M) {
    __shared__ float t[32][33];
    const int n0 = blockIdx.x * 32, k0 = blockIdx.y * 32;
    const int tid = threadIdx.x;
    const int tx = tid & 31, ty = tid >> 5;
    #pragma unroll
    for (int j = 0; j < 32; j += 8)
        t[ty + j][tx] = M[(size_t)(k0 + ty + j) * ND + n0 + tx];
    __syncthreads();
    #pragma unroll
    for (int rep = 0; rep < 2; rep++) {
        int idx = rep * 256 + tid;
        int nl = idx >> 4, kp = idx & 15;
        g_Mth[(size_t)(n0 + nl) * 256 + (k0 >> 1) + kp] =
            packh(t[2 * kp][nl], t[2 * kp + 1][nl]);
    }
}

// ---------------------------------------------------------------------------
// Kernel 1: gather + fp16-pack + norms (fused)  [R11 exact]
// ---------------------------------------------------------------------------
__global__ __launch_bounds__(256) void prep_kernel(
    const int* __restrict__ t1c, const int* __restrict__ t2c,
    const float* __restrict__ E)
{
    const int b = blockIdx.x, tid = threadIdx.x;
    __shared__ int i1s[NL], i2s[NL];
    if (tid < NL) { i1s[tid] = t1c[b * NL + tid]; i2s[tid] = t2c[b * NL + tid]; }
    __syncthreads();
    float s1 = 0.f, s2 = 0.f;
    #pragma unroll 2
    for (int l = 0; l < NL; l++) {
        float2 v1 = ((const float2*)(E + (size_t)i1s[l] * ND))[tid];
        float2 v2 = ((const float2*)(E + (size_t)i2s[l] * ND))[tid];
        s1 += v1.x * v1.x + v1.y * v1.y;
        s2 += v2.x * v2.x + v2.y * v2.y;
        size_t o = (size_t)(b * NL + l) * 256 + tid;
        g_A1h[o] = packh(v1.x, v1.y);
        g_B2h[o] = packh(v2.x, v2.y);
    }
    __shared__ float sh1[8], sh2[8];
    #pragma unroll
    for (int o = 16; o; o >>= 1) {
        s1 += __shfl_xor_sync(0xffffffffu, s1, o);
        s2 += __shfl_xor_sync(0xffffffffu, s2, o);
    }
    if ((tid & 31) == 0) { sh1[tid >> 5] = s1; sh2[tid >> 5] = s2; }
    __syncthreads();
    if (tid < 8) {
        s1 = sh1[tid]; s2 = sh2[tid];
        #pragma unroll
        for (int o = 4; o; o >>= 1) {
            s1 += __shfl_xor_sync(0xffu, s1, o);
            s2 += __shfl_xor_sync(0xffu, s2, o);
        }
        if (tid == 0) { g_inv_na[b] = rsqrtf(s1); g_inv_nb[b] = rsqrtf(s2); }
    }
}

// ---------------------------------------------------------------------------
// Kernel 2: GEMM1 — C = A1 @ Mt^T (both fp16), 128x256 tile, 512 thr [R11 exact]
// ---------------------------------------------------------------------------
#define G1_STAGE 49152
#define G1_SMEM  (2 * G1_STAGE + 1024)

__global__ __launch_bounds__(512, 1) void gemm1_kernel()
{
    extern __shared__ char smem_raw[];
    const uint32_t sb_raw = smem_u32(smem_raw);
    const uint32_t sb = (sb_raw + 1023) & ~1023u;
    const int tid = threadIdx.x;
    const int m0 = blockIdx.y * 128, n0 = blockIdx.x * 256;

    const char* srcA = (const char*)g_A1h + (size_t)m0 * 1024;
    const char* srcB = (const char*)g_Mth + (size_t)n0 * 1024;

    auto load_stage = [&](int c, int s) {
        const uint32_t stg = sb + s * G1_STAGE;
        #pragma unroll
        for (int q = 0; q < 2; q++) {     // A: 128 rows x 8 segs
            int sid = tid + q * 512;
            int r = sid >> 3, seg = sid & 7;
            uint32_t dst = stg + swz((uint32_t)(r * 128 + seg * 16));
            CP16(dst, srcA + (size_t)r * 1024 + c * 128 + seg * 16);
        }
        #pragma unroll
        for (int q = 0; q < 4; q++) {     // B: 256 rows x 8 segs
            int sid = tid + q * 512;
            int r = sid >> 3, seg = sid & 7;
            uint32_t dst = stg + 16384 + swz((uint32_t)(r * 128 + seg * 16));
            CP16(dst, srcB + (size_t)r * 1024 + c * 128 + seg * 16);
        }
    };

    float acc[2][8][4];
    #pragma unroll
    for (int i = 0; i < 2; i++)
        #pragma unroll
        for (int j = 0; j < 8; j++)
            #pragma unroll
            for (int q = 0; q < 4; q++) acc[i][j][q] = 0.f;

    load_stage(0, 0); CP_COMMIT();
    load_stage(1, 1); CP_COMMIT();
    CP_WAIT(1); __syncthreads();

    const int wid = tid >> 5, lane = tid & 31;
    const int m_base = (wid >> 2) * 32, n_base = (wid & 3) * 64;

    for (int c = 0; c < 8; c++) {
        chunk_g1(sb + (c & 1) * G1_STAGE, lane, m_base, n_base, acc);
        __syncthreads();
        if (c + 2 < 8) { load_stage(c + 2, c & 1); CP_COMMIT(); CP_WAIT(1); }
        else if (c == 6) { CP_WAIT(0); }
        __syncthreads();
    }

    // epilogue: fp16-pack acc -> g_Ch
    #pragma unroll
    for (int i = 0; i < 2; i++) {
        int gr = m0 + m_base + i * 16 + (lane >> 2);
        #pragma unroll
        for (int j8 = 0; j8 < 8; j8++) {
            int gc = n0 + n_base + j8 * 8 + (lane & 3) * 2;
            g_Ch[(size_t)gr * 256 + (gc >> 1)]       = packh(acc[i][j8][0], acc[i][j8][1]);
            g_Ch[(size_t)(gr + 8) * 256 + (gc >> 1)] = packh(acc[i][j8][2], acc[i][j8][3]);
        }
    }
}

// ---------------------------------------------------------------------------
// Kernel 3: GEMM2 — S[b] = tanh(scale * C[b] @ B2[b]^T), fused means
//   256 thr, 8 warps (4x2), warp tile 32x64, 2 CTAs/SM; 3-stage x 32KB
// ---------------------------------------------------------------------------
#define G2_STAGE 32768
#define G2_SMEM  (3 * G2_STAGE + 1024)

__global__ __launch_bounds__(256, 2) void gemm2_kernel(float* __restrict__ outS)
{
    extern __shared__ char smem_raw[];
    const uint32_t sb_raw = smem_u32(smem_raw);
    const uint32_t sb = (sb_raw + 1023) & ~1023u;
    char* smem = smem_raw + (sb - sb_raw);
    const int tid = threadIdx.x;
    const int b = blockIdx.x;

    const char* srcC = (const char*)g_Ch  + (size_t)b * NL * 1024;
    const char* srcB = (const char*)g_B2h + (size_t)b * NL * 1024;

    auto load_stage = [&](int c, int s) {
        const uint32_t stg = sb + s * G2_STAGE;
        #pragma unroll
        for (int q = 0; q < 4; q++) {
            int sid = tid + q * 256;
            int r = sid >> 3, seg = sid & 7;
            uint32_t dst = stg + swz((uint32_t)(r * 128 + seg * 16));
            size_t so = (size_t)r * 1024 + c * 128 + seg * 16;
            CP16(dst, srcC + so);
            CP16(dst + 16384, srcB + so);
        }
    };

    float acc[2][8][4];
    #pragma unroll
    for (int i = 0; i < 2; i++)
        #pragma unroll
        for (int j = 0; j < 8; j++)
            #pragma unroll
            for (int q = 0; q < 4; q++) acc[i][j][q] = 0.f;

    load_stage(0, 0); CP_COMMIT();
    load_stage(1, 1); CP_COMMIT();
    load_stage(2, 2); CP_COMMIT();
    CP_WAIT(2); __syncthreads();

    const int wid = tid >> 5, lane = tid & 31;
    const int m_base = (wid >> 1) * 32, n_base = (wid & 1) * 64;

    for (int c = 0; c < 8; c++) {
        chunk_g1(sb + (c % 3) * G2_STAGE, lane, m_base, n_base, acc);
        __syncthreads();
        if (c + 3 < 8)      { load_stage(c + 3, c % 3); CP_COMMIT(); CP_WAIT(2); }
        else if (c == 5)    { CP_WAIT(1); }
        else if (c == 6)    { CP_WAIT(0); }
        __syncthreads();
    }

    // epilogue: tanh + S store + fused row/col means
    float* rs = (float*)smem;
    float* cs = rs + 128;
    if (tid < 128) { rs[tid] = 0.f; cs[tid] = 0.f; }
    __syncthreads();

    const float scale = g_inv_na[b] * g_inv_nb[b];
    float* Sb = outS + (size_t)b * NL * NL;
    float cpart0[8], cpart1[8];
    #pragma unroll
    for (int j8 = 0; j8 < 8; j8++) { cpart0[j8] = 0.f; cpart1[j8] = 0.f; }
    float rpart[2][2] = {{0.f, 0.f}, {0.f, 0.f}};

    #pragma unroll
    for (int i = 0; i < 2; i++) {
        int r0 = m_base + i * 16 + (lane >> 2);
        #pragma unroll
        for (int j8 = 0; j8 < 8; j8++) {
            int col = n_base + j8 * 8 + (lane & 3) * 2;
            float v0 = tanhf(acc[i][j8][0] * scale);
            float v1 = tanhf(acc[i][j8][1] * scale);
            float v2 = tanhf(acc[i][j8][2] * scale);
            float v3 = tanhf(acc[i][j8][3] * scale);
            float* p = Sb + (size_t)r0 * NL + col;
            *(float2*)p = make_float2(v0, v1);
            *(float2*)(p + 8 * NL) = make_float2(v2, v3);
            rpart[i][0] += v0 + v1;
            rpart[i][1] += v2 + v3;
            cpart0[j8] += v0 + v2;
            cpart1[j8] += v1 + v3;
        }
    }
    #pragma unroll
    for (int i = 0; i < 2; i++) {
        atomicAdd(&rs[m_base + i * 16 + (lane >> 2)], rpart[i][0]);
        atomicAdd(&rs[m_base + i * 16 + (lane >> 2) + 8], rpart[i][1]);
    }
    #pragma unroll
    for (int j8 = 0; j8 < 8; j8++) {
        atomicAdd(&cs[n_base + j8 * 8 + (lane & 3) * 2], cpart0[j8]);
        atomicAdd(&cs[n_base + j8 * 8 + (lane & 3) * 2 + 1], cpart1[j8]);
    }
    __syncthreads();
    if (tid < 128) {
        g_rowm[b * NL + tid] = rs[tid] * (1.0f / NL);
        g_colm[b * NL + tid] = cs[tid] * (1.0f / NL);
    }
}

// ---------------------------------------------------------------------------
// Kernel 4: fused softmax (rows & cols concurrently) + weighted reduce + logits
// ---------------------------------------------------------------------------
__global__ __launch_bounds__(256) void final_kernel(
    const float* __restrict__ w, const float* __restrict__ bp,
    float* __restrict__ out)
{
    const int b = blockIdx.x, tid = threadIdx.x;
    __shared__ float rw[NL], cw[NL], red[256];
    // --- dual softmax: threads 0-127 -> rows, 128-255 -> cols ---
    const int h = tid >> 7, t = tid & 127;
    float v = h ? g_colm[b * NL + t] : g_rowm[b * NL + t];
    red[tid] = v;
    __syncthreads();
    #pragma unroll
    for (int s = 64; s; s >>= 1) {
        if (t < s) red[h * 128 + t] = fmaxf(red[h * 128 + t], red[h * 128 + t + s]);
        __syncthreads();
    }
    float mx = red[h * 128];
    __syncthreads();
    float e = expf(v - mx);
    red[tid] = e;
    __syncthreads();
    #pragma unroll
    for (int s = 64; s; s >>= 1) {
        if (t < s) red[h * 128 + t] += red[h * 128 + t + s];
        __syncthreads();
    }
    float sm = e / red[h * 128];
    if (h == 0) rw[t] = sm; else cw[t] = sm;
    __syncthreads();

    // --- weighted reduce from fp16 arrays (sequential reads) ---
    float ax = 0.f, ay = 0.f, bx = 0.f, by = 0.f;
    #pragma unroll 4
    for (int l = 0; l < NL; l++) {
        size_t o = (size_t)(b * NL + l) * 256 + tid;
        uint32_t av = g_A1h[o], bv = g_B2h[o];
        __half2 ah = *reinterpret_cast<__half2*>(&av);
        __half2 bh = *reinterpret_cast<__half2*>(&bv);
        float wr = rw[l], wc = cw[l];
        ax += wr * __half2float(ah.x);  ay += wr * __half2float(ah.y);
        bx += wc * __half2float(bh.x);  by += wc * __half2float(bh.y);
    }
    float2 wv = ((const float2*)w)[tid];
    float part = (ax * bx * wv.x + ay * by * wv.y) * (g_inv_na[b] * g_inv_nb[b]);
    __shared__ float sh[8];
    #pragma unroll
    for (int o = 16; o; o >>= 1) part += __shfl_xor_sync(0xffffffffu, part, o);
    if ((tid & 31) == 0) sh[tid >> 5] = part;
    __syncthreads();
    if (tid < 8) {
        part = sh[tid];
        #pragma unroll
        for (int o = 4; o; o >>= 1) part += __shfl_xor_sync(0xffu, part, o);
        if (tid == 0) out[b] = part + bp[0];
    }
}

// ---------------------------------------------------------------------------
extern "C" void kernel_launch(void* const* d_in, const int* in_sizes, int n_in,
                              void* d_out, int out_size)
{
    (void)in_sizes; (void)n_in; (void)out_size;
    const int*   t1c = (const int*)d_in[2];
    const int*   t2c = (const int*)d_in[3];
    const float* E   = (const float*)d_in[4];
    const float* M   = (const float*)d_in[5];
    const float* w   = (const float*)d_in[6];
    const float* bp  = (const float*)d_in[7];
    float* out  = (float*)d_out;
    float* outS = out + NB;   // output = concat(logits[512], S[512*128*128])

    cudaFuncSetAttribute(gemm1_kernel, cudaFuncAttributeMaxDynamicSharedMemorySize, G1_SMEM);
    cudaFuncSetAttribute(gemm2_kernel, cudaFuncAttributeMaxDynamicSharedMemorySize, G2_SMEM);

    prep_mt_kernel<<<dim3(16, 16), 256>>>(M);
    prep_kernel<<<NB, 256>>>(t1c, t2c, E);
    gemm1_kernel<<<dim3(2, 512), 512, G1_SMEM>>>();
    gemm2_kernel<<<NB, 256, G2_SMEM>>>(outS);
    final_kernel<<<NB, 256>>>(w, bp, out);
}

// round 16
// speedup vs baseline: 1.2264x; 1.0314x over previous
#include <cuda_runtime.h>
#include <cuda_fp16.h>
#include <math.h>
#include <stdint.h>

#define NB 512
#define NL 128
#define ND 512
#define NROWS ((size_t)NB * NL)   // 65536

// ---------------- scratch (static device globals) ----------------
// packed 2x fp16 per uint32; row = 256 uint32 = 512 cols = 1024 B
__device__ uint32_t g_A1h[NROWS * 256];   // gather(E,t1) fp16
__device__ uint32_t g_B2h[NROWS * 256];   // gather(E,t2) fp16
__device__ uint32_t g_Ch [NROWS * 256];   // C = A1 @ M, fp16
__device__ uint32_t g_Mth[ND * 256];      // Mt[n][k] fp16
__device__ float g_inv_na[NB], g_inv_nb[NB];
__device__ float g_rowm[NB * NL], g_colm[NB * NL];

// ---------------- helpers ----------------
__device__ __forceinline__ uint32_t smem_u32(const void* p) {
    uint32_t a;
    asm("{ .reg .u64 t; cvta.to.shared.u64 t, %1; cvt.u32.u64 %0, t; }" : "=r"(a) : "l"(p));
    return a;
}
__device__ __forceinline__ uint32_t swz(uint32_t o) { return o ^ ((o >> 3) & 0x70); }

#define CP16(dst, src) \
    asm volatile("cp.async.cg.shared.global [%0], [%1], 16;" :: "r"(dst), "l"(src))
#define CP_COMMIT() asm volatile("cp.async.commit_group;" ::: "memory")
#define CP_WAIT(n)  asm volatile("cp.async.wait_group %0;" :: "n"(n) : "memory")

__device__ __forceinline__ void ldm_x4(uint32_t* r, uint32_t addr) {
    asm volatile("ldmatrix.sync.aligned.m8n8.x4.shared.b16 {%0,%1,%2,%3}, [%4];"
        : "=r"(r[0]), "=r"(r[1]), "=r"(r[2]), "=r"(r[3]) : "r"(addr));
}
__device__ __forceinline__ void mma_f16(float* c, const uint32_t* a, const uint32_t* b) {
    asm volatile("mma.sync.aligned.m16n8k16.row.col.f32.f16.f16.f32 "
        "{%0,%1,%2,%3}, {%4,%5,%6,%7}, {%8,%9}, {%0,%1,%2,%3};"
        : "+f"(c[0]), "+f"(c[1]), "+f"(c[2]), "+f"(c[3])
        : "r"(a[0]), "r"(a[1]), "r"(a[2]), "r"(a[3]), "r"(b[0]), "r"(b[1]));
}
__device__ __forceinline__ uint32_t packh(float a, float b) {
    return ((uint32_t)__half_as_ushort(__float2half_rn(b)) << 16) |
           (uint32_t)__half_as_ushort(__float2half_rn(a));
}

// K=64 chunk, warp tile 32x64; A @ 0 (128 rows), B @ +16K
__device__ __forceinline__ void chunk_g1(uint32_t st, int lane, int m_base,
                                         int n_base, float acc[2][8][4]) {
    const int lrow = lane & 7, lmat = lane >> 3;
    const uint32_t a_row = (uint32_t)(m_base + (lmat & 1) * 8 + lrow) * 128;
    const uint32_t a_kb  = (uint32_t)((lmat >> 1) * 8) * 2;
    const uint32_t b_row = (uint32_t)(n_base + (lmat >> 1) * 8 + lrow) * 128;
    const uint32_t b_kb  = (uint32_t)((lmat & 1) * 8) * 2;
    #pragma unroll
    for (int ks = 0; ks < 4; ks++) {
        uint32_t Af[2][4];
        #pragma unroll
        for (int i = 0; i < 2; i++)
            ldm_x4(Af[i], st + swz(a_row + (uint32_t)i * 2048 + a_kb + ks * 32));
        #pragma unroll
        for (int j = 0; j < 4; j++) {
            uint32_t Bf[4];
            ldm_x4(Bf, st + 16384 + swz(b_row + (uint32_t)j * 2048 + b_kb + ks * 32));
            #pragma unroll
            for (int i = 0; i < 2; i++) {
                mma_f16(acc[i][2*j],   Af[i], &Bf[0]);
                mma_f16(acc[i][2*j+1], Af[i], &Bf[2]);
            }
        }
    }
}

// ---------------------------------------------------------------------------
// Kernel 0: transpose + fp16-pack att_mat -> g_Mth (Mt[n][k] = M[k][n])
// ---------------------------------------------------------------------------
__global__ __launch_bounds__(256) void prep_mt_kernel(const float* __restrict__ M) {
    __shared__ float t[32][33];
    const int n0 = blockIdx.x * 32, k0 = blockIdx.y * 32;
    const int tid = threadIdx.x;
    const int tx = tid & 31, ty = tid >> 5;
    #pragma unroll
    for (int j = 0; j < 32; j += 8)
        t[ty + j][tx] = M[(size_t)(k0 + ty + j) * ND + n0 + tx];
    __syncthreads();
    #pragma unroll
    for (int rep = 0; rep < 2; rep++) {
        int idx = rep * 256 + tid;
        int nl = idx >> 4, kp = idx & 15;
        g_Mth[(size_t)(n0 + nl) * 256 + (k0 >> 1) + kp] =
            packh(t[2 * kp][nl], t[2 * kp + 1][nl]);
    }
}

// ---------------------------------------------------------------------------
// Kernel 1: gather + fp16-pack + norms (fused)  [R11 exact]
// ---------------------------------------------------------------------------
__global__ __launch_bounds__(256) void prep_kernel(
    const int* __restrict__ t1c, const int* __restrict__ t2c,
    const float* __restrict__ E)
{
    const int b = blockIdx.x, tid = threadIdx.x;
    __shared__ int i1s[NL], i2s[NL];
    if (tid < NL) { i1s[tid] = t1c[b * NL + tid]; i2s[tid] = t2c[b * NL + tid]; }
    __syncthreads();
    float s1 = 0.f, s2 = 0.f;
    #pragma unroll 2
    for (int l = 0; l < NL; l++) {
        float2 v1 = ((const float2*)(E + (size_t)i1s[l] * ND))[tid];
        float2 v2 = ((const float2*)(E + (size_t)i2s[l] * ND))[tid];
        s1 += v1.x * v1.x + v1.y * v1.y;
        s2 += v2.x * v2.x + v2.y * v2.y;
        size_t o = (size_t)(b * NL + l) * 256 + tid;
        g_A1h[o] = packh(v1.x, v1.y);
        g_B2h[o] = packh(v2.x, v2.y);
    }
    __shared__ float sh1[8], sh2[8];
    #pragma unroll
    for (int o = 16; o; o >>= 1) {
        s1 += __shfl_xor_sync(0xffffffffu, s1, o);
        s2 += __shfl_xor_sync(0xffffffffu, s2, o);
    }
    if ((tid & 31) == 0) { sh1[tid >> 5] = s1; sh2[tid >> 5] = s2; }
    __syncthreads();
    if (tid < 8) {
        s1 = sh1[tid]; s2 = sh2[tid];
        #pragma unroll
        for (int o = 4; o; o >>= 1) {
            s1 += __shfl_xor_sync(0xffu, s1, o);
            s2 += __shfl_xor_sync(0xffu, s2, o);
        }
        if (tid == 0) { g_inv_na[b] = rsqrtf(s1); g_inv_nb[b] = rsqrtf(s2); }
    }
}

// ---------------------------------------------------------------------------
// Kernel 2: GEMM1 — C = A1 @ Mt^T (fp16), 128x128 tile, 256 thr, 2 CTAs/SM
//   8 warps (4x2), warp tile 32x64; 3-stage x 32KB (A 16K | B 16K)
// ---------------------------------------------------------------------------
#define G1_STAGE 32768
#define G1_SMEM  (3 * G1_STAGE + 1024)

__global__ __launch_bounds__(256, 2) void gemm1_kernel()
{
    extern __shared__ char smem_raw[];
    const uint32_t sb_raw = smem_u32(smem_raw);
    const uint32_t sb = (sb_raw + 1023) & ~1023u;
    const int tid = threadIdx.x;
    const int m0 = blockIdx.y * 128, n0 = blockIdx.x * 128;

    const char* srcA = (const char*)g_A1h + (size_t)m0 * 1024;
    const char* srcB = (const char*)g_Mth + (size_t)n0 * 1024;

    auto load_stage = [&](int c, int s) {
        const uint32_t stg = sb + s * G1_STAGE;
        #pragma unroll
        for (int q = 0; q < 4; q++) {
            int sid = tid + q * 256;
            int r = sid >> 3, seg = sid & 7;
            uint32_t dst = stg + swz((uint32_t)(r * 128 + seg * 16));
            size_t so = (size_t)r * 1024 + c * 128 + seg * 16;
            CP16(dst, srcA + so);
            CP16(dst + 16384, srcB + so);
        }
    };

    float acc[2][8][4];
    #pragma unroll
    for (int i = 0; i < 2; i++)
        #pragma unroll
        for (int j = 0; j < 8; j++)
            #pragma unroll
            for (int q = 0; q < 4; q++) acc[i][j][q] = 0.f;

    load_stage(0, 0); CP_COMMIT();
    load_stage(1, 1); CP_COMMIT();
    load_stage(2, 2); CP_COMMIT();
    CP_WAIT(2); __syncthreads();

    const int wid = tid >> 5, lane = tid & 31;
    const int m_base = (wid >> 1) * 32, n_base = (wid & 1) * 64;

    for (int c = 0; c < 8; c++) {
        chunk_g1(sb + (c % 3) * G1_STAGE, lane, m_base, n_base, acc);
        __syncthreads();
        if (c + 3 < 8)      { load_stage(c + 3, c % 3); CP_COMMIT(); CP_WAIT(2); }
        else if (c == 5)    { CP_WAIT(1); }
        else if (c == 6)    { CP_WAIT(0); }
        __syncthreads();
    }

    // epilogue: fp16-pack acc -> g_Ch
    #pragma unroll
    for (int i = 0; i < 2; i++) {
        int gr = m0 + m_base + i * 16 + (lane >> 2);
        #pragma unroll
        for (int j8 = 0; j8 < 8; j8++) {
            int gc = n0 + n_base + j8 * 8 + (lane & 3) * 2;
            g_Ch[(size_t)gr * 256 + (gc >> 1)]       = packh(acc[i][j8][0], acc[i][j8][1]);
            g_Ch[(size_t)(gr + 8) * 256 + (gc >> 1)] = packh(acc[i][j8][2], acc[i][j8][3]);
        }
    }
}

// ---------------------------------------------------------------------------
// Kernel 3: GEMM2 — S[b] = tanh(scale * C[b] @ B2[b]^T), fused means [R15 exact]
//   256 thr, 8 warps (4x2), warp tile 32x64, 2 CTAs/SM; 3-stage x 32KB
// ---------------------------------------------------------------------------
#define G2_STAGE 32768
#define G2_SMEM  (3 * G2_STAGE + 1024)

__global__ __launch_bounds__(256, 2) void gemm2_kernel(float* __restrict__ outS)
{
    extern __shared__ char smem_raw[];
    const uint32_t sb_raw = smem_u32(smem_raw);
    const uint32_t sb = (sb_raw + 1023) & ~1023u;
    char* smem = smem_raw + (sb - sb_raw);
    const int tid = threadIdx.x;
    const int b = blockIdx.x;

    const char* srcC = (const char*)g_Ch  + (size_t)b * NL * 1024;
    const char* srcB = (const char*)g_B2h + (size_t)b * NL * 1024;

    auto load_stage = [&](int c, int s) {
        const uint32_t stg = sb + s * G2_STAGE;
        #pragma unroll
        for (int q = 0; q < 4; q++) {
            int sid = tid + q * 256;
            int r = sid >> 3, seg = sid & 7;
            uint32_t dst = stg + swz((uint32_t)(r * 128 + seg * 16));
            size_t so = (size_t)r * 1024 + c * 128 + seg * 16;
            CP16(dst, srcC + so);
            CP16(dst + 16384, srcB + so);
        }
    };

    float acc[2][8][4];
    #pragma unroll
    for (int i = 0; i < 2; i++)
        #pragma unroll
        for (int j = 0; j < 8; j++)
            #pragma unroll
            for (int q = 0; q < 4; q++) acc[i][j][q] = 0.f;

    load_stage(0, 0); CP_COMMIT();
    load_stage(1, 1); CP_COMMIT();
    load_stage(2, 2); CP_COMMIT();
    CP_WAIT(2); __syncthreads();

    const int wid = tid >> 5, lane = tid & 31;
    const int m_base = (wid >> 1) * 32, n_base = (wid & 1) * 64;

    for (int c = 0; c < 8; c++) {
        chunk_g1(sb + (c % 3) * G2_STAGE, lane, m_base, n_base, acc);
        __syncthreads();
        if (c + 3 < 8)      { load_stage(c + 3, c % 3); CP_COMMIT(); CP_WAIT(2); }
        else if (c == 5)    { CP_WAIT(1); }
        else if (c == 6)    { CP_WAIT(0); }
        __syncthreads();
    }

    // epilogue: tanh + S store + fused row/col means
    float* rs = (float*)smem;
    float* cs = rs + 128;
    if (tid < 128) { rs[tid] = 0.f; cs[tid] = 0.f; }
    __syncthreads();

    const float scale = g_inv_na[b] * g_inv_nb[b];
    float* Sb = outS + (size_t)b * NL * NL;
    float cpart0[8], cpart1[8];
    #pragma unroll
    for (int j8 = 0; j8 < 8; j8++) { cpart0[j8] = 0.f; cpart1[j8] = 0.f; }
    float rpart[2][2] = {{0.f, 0.f}, {0.f, 0.f}};

    #pragma unroll
    for (int i = 0; i < 2; i++) {
        int r0 = m_base + i * 16 + (lane >> 2);
        #pragma unroll
        for (int j8 = 0; j8 < 8; j8++) {
            int col = n_base + j8 * 8 + (lane & 3) * 2;
            float v0 = tanhf(acc[i][j8][0] * scale);
            float v1 = tanhf(acc[i][j8][1] * scale);
            float v2 = tanhf(acc[i][j8][2] * scale);
            float v3 = tanhf(acc[i][j8][3] * scale);
            float* p = Sb + (size_t)r0 * NL + col;
            *(float2*)p = make_float2(v0, v1);
            *(float2*)(p + 8 * NL) = make_float2(v2, v3);
            rpart[i][0] += v0 + v1;
            rpart[i][1] += v2 + v3;
            cpart0[j8] += v0 + v2;
            cpart1[j8] += v1 + v3;
        }
    }
    #pragma unroll
    for (int i = 0; i < 2; i++) {
        atomicAdd(&rs[m_base + i * 16 + (lane >> 2)], rpart[i][0]);
        atomicAdd(&rs[m_base + i * 16 + (lane >> 2) + 8], rpart[i][1]);
    }
    #pragma unroll
    for (int j8 = 0; j8 < 8; j8++) {
        atomicAdd(&cs[n_base + j8 * 8 + (lane & 3) * 2], cpart0[j8]);
        atomicAdd(&cs[n_base + j8 * 8 + (lane & 3) * 2 + 1], cpart1[j8]);
    }
    __syncthreads();
    if (tid < 128) {
        g_rowm[b * NL + tid] = rs[tid] * (1.0f / NL);
        g_colm[b * NL + tid] = cs[tid] * (1.0f / NL);
    }
}

// ---------------------------------------------------------------------------
// Kernel 4: fused softmax (rows & cols concurrently) + weighted reduce + logits
// ---------------------------------------------------------------------------
__global__ __launch_bounds__(256) void final_kernel(
    const float* __restrict__ w, const float* __restrict__ bp,
    float* __restrict__ out)
{
    const int b = blockIdx.x, tid = threadIdx.x;
    __shared__ float rw[NL], cw[NL], red[256];
    // --- dual softmax: threads 0-127 -> rows, 128-255 -> cols ---
    const int h = tid >> 7, t = tid & 127;
    float v = h ? g_colm[b * NL + t] : g_rowm[b * NL + t];
    red[tid] = v;
    __syncthreads();
    #pragma unroll
    for (int s = 64; s; s >>= 1) {
        if (t < s) red[h * 128 + t] = fmaxf(red[h * 128 + t], red[h * 128 + t + s]);
        __syncthreads();
    }
    float mx = red[h * 128];
    __syncthreads();
    float e = expf(v - mx);
    red[tid] = e;
    __syncthreads();
    #pragma unroll
    for (int s = 64; s; s >>= 1) {
        if (t < s) red[h * 128 + t] += red[h * 128 + t + s];
        __syncthreads();
    }
    float sm = e / red[h * 128];
    if (h == 0) rw[t] = sm; else cw[t] = sm;
    __syncthreads();

    // --- weighted reduce from fp16 arrays (sequential reads) ---
    float ax = 0.f, ay = 0.f, bx = 0.f, by = 0.f;
    #pragma unroll 4
    for (int l = 0; l < NL; l++) {
        size_t o = (size_t)(b * NL + l) * 256 + tid;
        uint32_t av = g_A1h[o], bv = g_B2h[o];
        __half2 ah = *reinterpret_cast<__half2*>(&av);
        __half2 bh = *reinterpret_cast<__half2*>(&bv);
        float wr = rw[l], wc = cw[l];
        ax += wr * __half2float(ah.x);  ay += wr * __half2float(ah.y);
        bx += wc * __half2float(bh.x);  by += wc * __half2float(bh.y);
    }
    float2 wv = ((const float2*)w)[tid];
    float part = (ax * bx * wv.x + ay * by * wv.y) * (g_inv_na[b] * g_inv_nb[b]);
    __shared__ float sh[8];
    #pragma unroll
    for (int o = 16; o; o >>= 1) part += __shfl_xor_sync(0xffffffffu, part, o);
    if ((tid & 31) == 0) sh[tid >> 5] = part;
    __syncthreads();
    if (tid < 8) {
        part = sh[tid];
        #pragma unroll
        for (int o = 4; o; o >>= 1) part += __shfl_xor_sync(0xffu, part, o);
        if (tid == 0) out[b] = part + bp[0];
    }
}

// ---------------------------------------------------------------------------
extern "C" void kernel_launch(void* const* d_in, const int* in_sizes, int n_in,
                              void* d_out, int out_size)
{
    (void)in_sizes; (void)n_in; (void)out_size;
    const int*   t1c = (const int*)d_in[2];
    const int*   t2c = (const int*)d_in[3];
    const float* E   = (const float*)d_in[4];
    const float* M   = (const float*)d_in[5];
    const float* w   = (const float*)d_in[6];
    const float* bp  = (const float*)d_in[7];
    float* out  = (float*)d_out;
    float* outS = out + NB;   // output = concat(logits[512], S[512*128*128])

    cudaFuncSetAttribute(gemm1_kernel, cudaFuncAttributeMaxDynamicSharedMemorySize, G1_SMEM);
    cudaFuncSetAttribute(gemm2_kernel, cudaFuncAttributeMaxDynamicSharedMemorySize, G2_SMEM);

    prep_mt_kernel<<<dim3(16, 16), 256>>>(M);
    prep_kernel<<<NB, 256>>>(t1c, t2c, E);
    gemm1_kernel<<<dim3(4, 512), 256, G1_SMEM>>>();
    gemm2_kernel<<<NB, 256, G2_SMEM>>>(outS);
    final_kernel<<<NB, 256>>>(w, bp, out);
}

// round 17
// speedup vs baseline: 1.2631x; 1.0299x over previous
#include <cuda_runtime.h>
#include <cuda_fp16.h>
#include <math.h>
#include <stdint.h>

#define NB 512
#define NL 128
#define ND 512
#define NROWS ((size_t)NB * NL)   // 65536

// ---------------- scratch (static device globals) ----------------
// packed 2x fp16 per uint32; row = 256 uint32 = 512 cols = 1024 B
__device__ uint32_t g_A1h[NROWS * 256];   // gather(E,t1) fp16
__device__ uint32_t g_B2h[NROWS * 256];   // gather(E,t2) fp16
__device__ uint32_t g_Ch [NROWS * 256];   // C = A1 @ M, fp16
__device__ uint32_t g_Mth[ND * 256];      // Mt[n][k] fp16
__device__ float g_nsq1[NB * 4], g_nsq2[NB * 4];   // norm^2 partials (4 per batch)
__device__ float g_rowm[NB * NL], g_colm[NB * NL];

// ---------------- helpers ----------------
__device__ __forceinline__ uint32_t smem_u32(const void* p) {
    uint32_t a;
    asm("{ .reg .u64 t; cvta.to.shared.u64 t, %1; cvt.u32.u64 %0, t; }" : "=r"(a) : "l"(p));
    return a;
}
__device__ __forceinline__ uint32_t swz(uint32_t o) { return o ^ ((o >> 3) & 0x70); }

#define CP16(dst, src) \
    asm volatile("cp.async.cg.shared.global [%0], [%1], 16;" :: "r"(dst), "l"(src))
#define CP_COMMIT() asm volatile("cp.async.commit_group;" ::: "memory")
#define CP_WAIT(n)  asm volatile("cp.async.wait_group %0;" :: "n"(n) : "memory")

__device__ __forceinline__ void ldm_x4(uint32_t* r, uint32_t addr) {
    asm volatile("ldmatrix.sync.aligned.m8n8.x4.shared.b16 {%0,%1,%2,%3}, [%4];"
        : "=r"(r[0]), "=r"(r[1]), "=r"(r[2]), "=r"(r[3]) : "r"(addr));
}
__device__ __forceinline__ void mma_f16(float* c, const uint32_t* a, const uint32_t* b) {
    asm volatile("mma.sync.aligned.m16n8k16.row.col.f32.f16.f16.f32 "
        "{%0,%1,%2,%3}, {%4,%5,%6,%7}, {%8,%9}, {%0,%1,%2,%3};"
        : "+f"(c[0]), "+f"(c[1]), "+f"(c[2]), "+f"(c[3])
        : "r"(a[0]), "r"(a[1]), "r"(a[2]), "r"(a[3]), "r"(b[0]), "r"(b[1]));
}
__device__ __forceinline__ uint32_t packh(float a, float b) {
    return ((uint32_t)__half_as_ushort(__float2half_rn(b)) << 16) |
           (uint32_t)__half_as_ushort(__float2half_rn(a));
}

// K=64 chunk, warp tile 32x64; A @ 0 (128 rows), B @ +16K
__device__ __forceinline__ void chunk_g1(uint32_t st, int lane, int m_base,
                                         int n_base, float acc[2][8][4]) {
    const int lrow = lane & 7, lmat = lane >> 3;
    const uint32_t a_row = (uint32_t)(m_base + (lmat & 1) * 8 + lrow) * 128;
    const uint32_t a_kb  = (uint32_t)((lmat >> 1) * 8) * 2;
    const uint32_t b_row = (uint32_t)(n_base + (lmat >> 1) * 8 + lrow) * 128;
    const uint32_t b_kb  = (uint32_t)((lmat & 1) * 8) * 2;
    #pragma unroll
    for (int ks = 0; ks < 4; ks++) {
        uint32_t Af[2][4];
        #pragma unroll
        for (int i = 0; i < 2; i++)
            ldm_x4(Af[i], st + swz(a_row + (uint32_t)i * 2048 + a_kb + ks * 32));
        #pragma unroll
        for (int j = 0; j < 4; j++) {
            uint32_t Bf[4];
            ldm_x4(Bf, st + 16384 + swz(b_row + (uint32_t)j * 2048 + b_kb + ks * 32));
            #pragma unroll
            for (int i = 0; i < 2; i++) {
                mma_f16(acc[i][2*j],   Af[i], &Bf[0]);
                mma_f16(acc[i][2*j+1], Af[i], &Bf[2]);
            }
        }
    }
}

// ---------------------------------------------------------------------------
// Kernel 0: transpose + fp16-pack att_mat -> g_Mth (Mt[n][k] = M[k][n])
// ---------------------------------------------------------------------------
__global__ __launch_bounds__(256) void prep_mt_kernel(const float* __restrict__ M) {
    __shared__ float t[32][33];
    const int n0 = blockIdx.x * 32, k0 = blockIdx.y * 32;
    const int tid = threadIdx.x;
    const int tx = tid & 31, ty = tid >> 5;
    #pragma unroll
    for (int j = 0; j < 32; j += 8)
        t[ty + j][tx] = M[(size_t)(k0 + ty + j) * ND + n0 + tx];
    __syncthreads();
    #pragma unroll
    for (int rep = 0; rep < 2; rep++) {
        int idx = rep * 256 + tid;
        int nl = idx >> 4, kp = idx & 15;
        g_Mth[(size_t)(n0 + nl) * 256 + (k0 >> 1) + kp] =
            packh(t[2 * kp][nl], t[2 * kp + 1][nl]);
    }
}

// ---------------------------------------------------------------------------
// Kernel 1: gather + fp16-pack + norm partials (4 CTAs per batch)
// ---------------------------------------------------------------------------
__global__ __launch_bounds__(256) void prep_kernel(
    const int* __restrict__ t1c, const int* __restrict__ t2c,
    const float* __restrict__ E)
{
    const int part = blockIdx.x, b = blockIdx.y, tid = threadIdx.x;
    const int l0 = part * 32;
    __shared__ int i1s[32], i2s[32];
    if (tid < 32) {
        i1s[tid] = t1c[b * NL + l0 + tid];
        i2s[tid] = t2c[b * NL + l0 + tid];
    }
    __syncthreads();
    float s1 = 0.f, s2 = 0.f;
    #pragma unroll 4
    for (int l = 0; l < 32; l++) {
        float2 v1 = ((const float2*)(E + (size_t)i1s[l] * ND))[tid];
        float2 v2 = ((const float2*)(E + (size_t)i2s[l] * ND))[tid];
        s1 += v1.x * v1.x + v1.y * v1.y;
        s2 += v2.x * v2.x + v2.y * v2.y;
        size_t o = (size_t)(b * NL + l0 + l) * 256 + tid;
        g_A1h[o] = packh(v1.x, v1.y);
        g_B2h[o] = packh(v2.x, v2.y);
    }
    __shared__ float sh1[8], sh2[8];
    #pragma unroll
    for (int o = 16; o; o >>= 1) {
        s1 += __shfl_xor_sync(0xffffffffu, s1, o);
        s2 += __shfl_xor_sync(0xffffffffu, s2, o);
    }
    if ((tid & 31) == 0) { sh1[tid >> 5] = s1; sh2[tid >> 5] = s2; }
    __syncthreads();
    if (tid < 8) {
        s1 = sh1[tid]; s2 = sh2[tid];
        #pragma unroll
        for (int o = 4; o; o >>= 1) {
            s1 += __shfl_xor_sync(0xffu, s1, o);
            s2 += __shfl_xor_sync(0xffu, s2, o);
        }
        if (tid == 0) { g_nsq1[b * 4 + part] = s1; g_nsq2[b * 4 + part] = s2; }
    }
}

// ---------------------------------------------------------------------------
// Kernel 2: GEMM1 — C = A1 @ Mt^T (fp16), 128x128 tile, 256 thr, 2 CTAs/SM
// ---------------------------------------------------------------------------
#define G1_STAGE 32768
#define G1_SMEM  (3 * G1_STAGE + 1024)

__global__ __launch_bounds__(256, 2) void gemm1_kernel()
{
    extern __shared__ char smem_raw[];
    const uint32_t sb_raw = smem_u32(smem_raw);
    const uint32_t sb = (sb_raw + 1023) & ~1023u;
    const int tid = threadIdx.x;
    const int m0 = blockIdx.y * 128, n0 = blockIdx.x * 128;

    const char* srcA = (const char*)g_A1h + (size_t)m0 * 1024;
    const char* srcB = (const char*)g_Mth + (size_t)n0 * 1024;

    auto load_stage = [&](int c, int s) {
        const uint32_t stg = sb + s * G1_STAGE;
        #pragma unroll
        for (int q = 0; q < 4; q++) {
            int sid = tid + q * 256;
            int r = sid >> 3, seg = sid & 7;
            uint32_t dst = stg + swz((uint32_t)(r * 128 + seg * 16));
            size_t so = (size_t)r * 1024 + c * 128 + seg * 16;
            CP16(dst, srcA + so);
            CP16(dst + 16384, srcB + so);
        }
    };

    float acc[2][8][4];
    #pragma unroll
    for (int i = 0; i < 2; i++)
        #pragma unroll
        for (int j = 0; j < 8; j++)
            #pragma unroll
            for (int q = 0; q < 4; q++) acc[i][j][q] = 0.f;

    load_stage(0, 0); CP_COMMIT();
    load_stage(1, 1); CP_COMMIT();
    load_stage(2, 2); CP_COMMIT();
    CP_WAIT(2); __syncthreads();

    const int wid = tid >> 5, lane = tid & 31;
    const int m_base = (wid >> 1) * 32, n_base = (wid & 1) * 64;

    for (int c = 0; c < 8; c++) {
        chunk_g1(sb + (c % 3) * G1_STAGE, lane, m_base, n_base, acc);
        __syncthreads();
        if (c + 3 < 8)      { load_stage(c + 3, c % 3); CP_COMMIT(); CP_WAIT(2); }
        else if (c == 5)    { CP_WAIT(1); }
        else if (c == 6)    { CP_WAIT(0); }
        __syncthreads();
    }

    // epilogue: fp16-pack acc -> g_Ch
    #pragma unroll
    for (int i = 0; i < 2; i++) {
        int gr = m0 + m_base + i * 16 + (lane >> 2);
        #pragma unroll
        for (int j8 = 0; j8 < 8; j8++) {
            int gc = n0 + n_base + j8 * 8 + (lane & 3) * 2;
            g_Ch[(size_t)gr * 256 + (gc >> 1)]       = packh(acc[i][j8][0], acc[i][j8][1]);
            g_Ch[(size_t)(gr + 8) * 256 + (gc >> 1)] = packh(acc[i][j8][2], acc[i][j8][3]);
        }
    }
}

// ---------------------------------------------------------------------------
// Kernel 3: GEMM2 — S[b] = tanh(scale * C[b] @ B2[b]^T), fused means
//   256 thr, 8 warps (4x2), warp tile 32x64, 2 CTAs/SM; 3-stage x 32KB
// ---------------------------------------------------------------------------
#define G2_STAGE 32768
#define G2_SMEM  (3 * G2_STAGE + 1024)

__global__ __launch_bounds__(256, 2) void gemm2_kernel(float* __restrict__ outS)
{
    extern __shared__ char smem_raw[];
    const uint32_t sb_raw = smem_u32(smem_raw);
    const uint32_t sb = (sb_raw + 1023) & ~1023u;
    char* smem = smem_raw + (sb - sb_raw);
    const int tid = threadIdx.x;
    const int b = blockIdx.x;

    const char* srcC = (const char*)g_Ch  + (size_t)b * NL * 1024;
    const char* srcB = (const char*)g_B2h + (size_t)b * NL * 1024;

    auto load_stage = [&](int c, int s) {
        const uint32_t stg = sb + s * G2_STAGE;
        #pragma unroll
        for (int q = 0; q < 4; q++) {
            int sid = tid + q * 256;
            int r = sid >> 3, seg = sid & 7;
            uint32_t dst = stg + swz((uint32_t)(r * 128 + seg * 16));
            size_t so = (size_t)r * 1024 + c * 128 + seg * 16;
            CP16(dst, srcC + so);
            CP16(dst + 16384, srcB + so);
        }
    };

    float acc[2][8][4];
    #pragma unroll
    for (int i = 0; i < 2; i++)
        #pragma unroll
        for (int j = 0; j < 8; j++)
            #pragma unroll
            for (int q = 0; q < 4; q++) acc[i][j][q] = 0.f;

    load_stage(0, 0); CP_COMMIT();
    load_stage(1, 1); CP_COMMIT();
    load_stage(2, 2); CP_COMMIT();
    CP_WAIT(2); __syncthreads();

    const int wid = tid >> 5, lane = tid & 31;
    const int m_base = (wid >> 1) * 32, n_base = (wid & 1) * 64;

    for (int c = 0; c < 8; c++) {
        chunk_g1(sb + (c % 3) * G2_STAGE, lane, m_base, n_base, acc);
        __syncthreads();
        if (c + 3 < 8)      { load_stage(c + 3, c % 3); CP_COMMIT(); CP_WAIT(2); }
        else if (c == 5)    { CP_WAIT(1); }
        else if (c == 6)    { CP_WAIT(0); }
        __syncthreads();
    }

    // epilogue: tanh + S store + fused row/col means
    float* rs = (float*)smem;
    float* cs = rs + 128;
    if (tid < 128) { rs[tid] = 0.f; cs[tid] = 0.f; }
    __syncthreads();

    const float4 q1 = *(const float4*)&g_nsq1[b * 4];
    const float4 q2 = *(const float4*)&g_nsq2[b * 4];
    const float scale = rsqrtf(q1.x + q1.y + q1.z + q1.w) *
                        rsqrtf(q2.x + q2.y + q2.z + q2.w);
    float* Sb = outS + (size_t)b * NL * NL;
    float cpart0[8], cpart1[8];
    #pragma unroll
    for (int j8 = 0; j8 < 8; j8++) { cpart0[j8] = 0.f; cpart1[j8] = 0.f; }
    float rpart[2][2] = {{0.f, 0.f}, {0.f, 0.f}};

    #pragma unroll
    for (int i = 0; i < 2; i++) {
        int r0 = m_base + i * 16 + (lane >> 2);
        #pragma unroll
        for (int j8 = 0; j8 < 8; j8++) {
            int col = n_base + j8 * 8 + (lane & 3) * 2;
            float v0 = tanhf(acc[i][j8][0] * scale);
            float v1 = tanhf(acc[i][j8][1] * scale);
            float v2 = tanhf(acc[i][j8][2] * scale);
            float v3 = tanhf(acc[i][j8][3] * scale);
            float* p = Sb + (size_t)r0 * NL + col;
            *(float2*)p = make_float2(v0, v1);
            *(float2*)(p + 8 * NL) = make_float2(v2, v3);
            rpart[i][0] += v0 + v1;
            rpart[i][1] += v2 + v3;
            cpart0[j8] += v0 + v2;
            cpart1[j8] += v1 + v3;
        }
    }
    #pragma unroll
    for (int i = 0; i < 2; i++) {
        atomicAdd(&rs[m_base + i * 16 + (lane >> 2)], rpart[i][0]);
        atomicAdd(&rs[m_base + i * 16 + (lane >> 2) + 8], rpart[i][1]);
    }
    #pragma unroll
    for (int j8 = 0; j8 < 8; j8++) {
        atomicAdd(&cs[n_base + j8 * 8 + (lane & 3) * 2], cpart0[j8]);
        atomicAdd(&cs[n_base + j8 * 8 + (lane & 3) * 2 + 1], cpart1[j8]);
    }
    __syncthreads();
    if (tid < 128) {
        g_rowm[b * NL + tid] = rs[tid] * (1.0f / NL);
        g_colm[b * NL + tid] = cs[tid] * (1.0f / NL);
    }
}

// ---------------------------------------------------------------------------
// Kernel 4: fused softmax (rows & cols concurrently) + weighted reduce + logits
// ---------------------------------------------------------------------------
__global__ __launch_bounds__(256) void final_kernel(
    const float* __restrict__ w, const float* __restrict__ bp,
    float* __restrict__ out)
{
    const int b = blockIdx.x, tid = threadIdx.x;
    __shared__ float rw[NL], cw[NL], red[256];
    // --- dual softmax: threads 0-127 -> rows, 128-255 -> cols ---
    const int h = tid >> 7, t = tid & 127;
    float v = h ? g_colm[b * NL + t] : g_rowm[b * NL + t];
    red[tid] = v;
    __syncthreads();
    #pragma unroll
    for (int s = 64; s; s >>= 1) {
        if (t < s) red[h * 128 + t] = fmaxf(red[h * 128 + t], red[h * 128 + t + s]);
        __syncthreads();
    }
    float mx = red[h * 128];
    __syncthreads();
    float e = expf(v - mx);
    red[tid] = e;
    __syncthreads();
    #pragma unroll
    for (int s = 64; s; s >>= 1) {
        if (t < s) red[h * 128 + t] += red[h * 128 + t + s];
        __syncthreads();
    }
    float sm = e / red[h * 128];
    if (h == 0) rw[t] = sm; else cw[t] = sm;
    __syncthreads();

    // --- weighted reduce from fp16 arrays (sequential reads) ---
    float ax = 0.f, ay = 0.f, bx = 0.f, by = 0.f;
    #pragma unroll 8
    for (int l = 0; l < NL; l++) {
        size_t o = (size_t)(b * NL + l) * 256 + tid;
        uint32_t av = g_A1h[o], bv = g_B2h[o];
        __half2 ah = *reinterpret_cast<__half2*>(&av);
        __half2 bh = *reinterpret_cast<__half2*>(&bv);
        float wr = rw[l], wc = cw[l];
        ax += wr * __half2float(ah.x);  ay += wr * __half2float(ah.y);
        bx += wc * __half2float(bh.x);  by += wc * __half2float(bh.y);
    }
    const float4 q1 = *(const float4*)&g_nsq1[b * 4];
    const float4 q2 = *(const float4*)&g_nsq2[b * 4];
    const float scale = rsqrtf(q1.x + q1.y + q1.z + q1.w) *
                        rsqrtf(q2.x + q2.y + q2.z + q2.w);
    float2 wv = ((const float2*)w)[tid];
    float part = (ax * bx * wv.x + ay * by * wv.y) * scale;
    __shared__ float sh[8];
    #pragma unroll
    for (int o = 16; o; o >>= 1) part += __shfl_xor_sync(0xffffffffu, part, o);
    if ((tid & 31) == 0) sh[tid >> 5] = part;
    __syncthreads();
    if (tid < 8) {
        part = sh[tid];
        #pragma unroll
        for (int o = 4; o; o >>= 1) part += __shfl_xor_sync(0xffu, part, o);
        if (tid == 0) out[b] = part + bp[0];
    }
}

// ---------------------------------------------------------------------------
extern "C" void kernel_launch(void* const* d_in, const int* in_sizes, int n_in,
                              void* d_out, int out_size)
{
    (void)in_sizes; (void)n_in; (void)out_size;
    const int*   t1c = (const int*)d_in[2];
    const int*   t2c = (const int*)d_in[3];
    const float* E   = (const float*)d_in[4];
    const float* M   = (const float*)d_in[5];
    const float* w   = (const float*)d_in[6];
    const float* bp  = (const float*)d_in[7];
    float* out  = (float*)d_out;
    float* outS = out + NB;   // output = concat(logits[512], S[512*128*128])

    cudaFuncSetAttribute(gemm1_kernel, cudaFuncAttributeMaxDynamicSharedMemorySize, G1_SMEM);
    cudaFuncSetAttribute(gemm2_kernel, cudaFuncAttributeMaxDynamicSharedMemorySize, G2_SMEM);

    prep_mt_kernel<<<dim3(16, 16), 256>>>(M);
    prep_kernel<<<dim3(4, NB), 256>>>(t1c, t2c, E);
    gemm1_kernel<<<dim3(4, 512), 256, G1_SMEM>>>();
    gemm2_kernel<<<NB, 256, G2_SMEM>>>(outS);
    final_kernel<<<NB, 256>>>(w, bp, out);
}